// round 1
// baseline (speedup 1.0000x reference)
#include <cuda_runtime.h>
#include <math.h>

#define FULL 0xffffffffu

static constexpr int D    = 32;
static constexpr int P    = 16;
static constexpr int MAXB = 16384;

// ---------------- scratch (__device__ globals; no allocations) ----------------
__device__ float4 g_Utab0[MAXB * 32];   // per-b, per-lane float4 (4 gates)
__device__ float4 g_Utab1[MAXB * 32];
__device__ float4 g_Rtab0[32 * 32];     // rel contribution tables: [idx][lane] -> 4 gates
__device__ float4 g_Etab0[32 * 32];     // ent (seed/tail) contribution tables
__device__ float4 g_Rtab1[32 * 32];
__device__ float4 g_Etab1[32 * 32];
__device__ float  g_final0[MAXB * 32];
__device__ float  g_final1[MAXB * 32];
__device__ float  g_lossbuf[MAXB];

__device__ __forceinline__ float sigf(float x) { return 1.0f / (1.0f + __expf(-x)); }

__device__ __forceinline__ float4 f4add(float4 a, float4 b) {
    return make_float4(a.x + b.x, a.y + b.y, a.z + b.z, a.w + b.w);
}
__device__ __forceinline__ float4 f4add3(float4 a, float4 b, float4 c) {
    return make_float4(a.x + b.x + c.x, a.y + b.y + c.y, a.z + b.z + c.z, a.w + b.w + c.w);
}

// ---------------- precompute E/R contribution tables (tiny) ----------------
// blockIdx.x: 0 -> Rtab0, 1 -> Etab0, 2 -> Rtab1, 3 -> Etab1
__global__ void precompute_tables_kernel(const float* __restrict__ rel_table,
                                         const float* __restrict__ ent_table,
                                         const float* __restrict__ wih0,
                                         const float* __restrict__ wih1) {
    int tid   = threadIdx.x;          // 1024
    int which = blockIdx.x;
    int r     = tid >> 5;             // table row index 0..31
    int lane  = tid & 31;             // hidden index 0..31
    const float* w   = (which < 2) ? wih0 : wih1;
    const float* src = (which & 1) ? ent_table : rel_table;
    int colofs       = (which & 1) ? 32 : 0;   // ent -> second half of x, rel -> first half

    float4 acc = make_float4(0.f, 0.f, 0.f, 0.f);
    #pragma unroll
    for (int k = 0; k < 32; k++) {
        float x = src[r * 32 + k];
        acc.x += x * w[(0 * 32 + lane) * 64 + colofs + k];
        acc.y += x * w[(1 * 32 + lane) * 64 + colofs + k];
        acc.z += x * w[(2 * 32 + lane) * 64 + colofs + k];
        acc.w += x * w[(3 * 32 + lane) * 64 + colofs + k];
    }
    float4* dst = (which == 0) ? g_Rtab0 : (which == 1) ? g_Etab0
                : (which == 2) ? g_Rtab1 : g_Etab1;
    dst[tid] = acc;
}

// ---------------- precompute per-b user contribution (both hops) ----------------
__global__ __launch_bounds__(256) void precompute_u_kernel(
        const float* __restrict__ user_table,
        const float* __restrict__ wih0,
        const float* __restrict__ wih1,
        const int* __restrict__ users, int B) {
    __shared__ float4 w0[32 * 32];  // [k][lane] -> 4 gate weights, column k of W_ih[:, :32]
    __shared__ float4 w1[32 * 32];
    int tid = threadIdx.x;
    for (int i = tid; i < 32 * 32; i += 256) {
        int k = i >> 5, l = i & 31;
        w0[i] = make_float4(wih0[l * 64 + k], wih0[(l + 32) * 64 + k],
                            wih0[(l + 64) * 64 + k], wih0[(l + 96) * 64 + k]);
        w1[i] = make_float4(wih1[l * 64 + k], wih1[(l + 32) * 64 + k],
                            wih1[(l + 64) * 64 + k], wih1[(l + 96) * 64 + k]);
    }
    __syncthreads();

    int wid = tid >> 5, lane = tid & 31;
    int b = blockIdx.x * 8 + wid;
    if (b >= B) return;
    float u = user_table[users[b] * 32 + lane];
    float4 a0 = make_float4(0.f, 0.f, 0.f, 0.f);
    float4 a1 = make_float4(0.f, 0.f, 0.f, 0.f);
    #pragma unroll
    for (int k = 0; k < 32; k++) {
        float uk = __shfl_sync(FULL, u, k);
        float4 q0 = w0[k * 32 + lane];
        float4 q1 = w1[k * 32 + lane];
        a0.x += uk * q0.x; a0.y += uk * q0.y; a0.z += uk * q0.z; a0.w += uk * q0.w;
        a1.x += uk * q1.x; a1.y += uk * q1.y; a1.z += uk * q1.z; a1.w += uk * q1.w;
    }
    g_Utab0[b * 32 + lane] = a0;
    g_Utab1[b * 32 + lane] = a1;
}

// ---------------- main hop kernel: one block per batch row ----------------
// lane = hidden dim; each warp handles 2 paths; 8 warps = 16 paths.
template <int NSTEP, int STRIDE, int HOP>
__global__ __launch_bounds__(256) void hop_kernel(
        const float* __restrict__ whh,
        const float* __restrict__ b_ih,
        const float* __restrict__ b_hh,
        const int* __restrict__ items,
        const int* __restrict__ lp) {
    __shared__ float4 whh_sm[32 * 32];   // [k][lane] -> 4 gate weights, column k of W_hh
    __shared__ float  red[8][32];

    int tid = threadIdx.x;
    for (int i = tid; i < 32 * 32; i += 256) {
        int k = i >> 5, l = i & 31;
        whh_sm[i] = make_float4(whh[l * 32 + k], whh[(l + 32) * 32 + k],
                                whh[(l + 64) * 32 + k], whh[(l + 96) * 32 + k]);
    }
    __syncthreads();

    int wid = tid >> 5, lane = tid & 31;
    int b = blockIdx.x;
    int item = __ldg(&items[b]);

    const float4* Utab = HOP ? g_Utab1 : g_Utab0;
    const float4* Rtab = HOP ? g_Rtab1 : g_Rtab0;
    const float4* Etab = HOP ? g_Etab1 : g_Etab0;

    float4 bias = make_float4(b_ih[lane]      + b_hh[lane],
                              b_ih[32 + lane] + b_hh[32 + lane],
                              b_ih[64 + lane] + b_hh[64 + lane],
                              b_ih[96 + lane] + b_hh[96 + lane]);
    float4 base0 = f4add(bias, Utab[b * 32 + lane]);   // step-0 gate base (h = 0)

    int p0 = wid * 2, p1 = p0 + 1;
    const int* lpb = lp + (size_t)item * (P * STRIDE);
    int i0[STRIDE], i1[STRIDE];
    #pragma unroll
    for (int j = 0; j < STRIDE; j++) {
        i0[j] = __ldg(&lpb[p0 * STRIDE + j]);
        i1[j] = __ldg(&lpb[p1 * STRIDE + j]);
    }

    // ---- step 0: gates = bias + U[b] + E[seed], h = c = 0 ----
    float4 A0 = f4add(base0, Etab[i0[0] * 32 + lane]);
    float4 A1 = f4add(base0, Etab[i1[0] * 32 + lane]);
    float c0 = sigf(A0.x) * tanhf(A0.z);
    float h0 = sigf(A0.w) * tanhf(c0);
    float c1 = sigf(A1.x) * tanhf(A1.z);
    float h1 = sigf(A1.w) * tanhf(c1);

    // ---- steps 1..NSTEP-1: gates = bias + R[rel] + E[tail] + h @ W_hh^T ----
    #pragma unroll
    for (int s = 1; s < NSTEP; s++) {
        float4 B0 = f4add3(bias, Rtab[i0[2 * s - 1] * 32 + lane], Etab[i0[2 * s] * 32 + lane]);
        float4 B1 = f4add3(bias, Rtab[i1[2 * s - 1] * 32 + lane], Etab[i1[2 * s] * 32 + lane]);
        #pragma unroll
        for (int k = 0; k < 32; k++) {
            float hk0 = __shfl_sync(FULL, h0, k);
            float hk1 = __shfl_sync(FULL, h1, k);
            float4 w = whh_sm[k * 32 + lane];
            B0.x += hk0 * w.x; B0.y += hk0 * w.y; B0.z += hk0 * w.z; B0.w += hk0 * w.w;
            B1.x += hk1 * w.x; B1.y += hk1 * w.y; B1.z += hk1 * w.z; B1.w += hk1 * w.w;
        }
        c0 = sigf(B0.y) * c0 + sigf(B0.x) * tanhf(B0.z);
        h0 = sigf(B0.w) * tanhf(c0);
        c1 = sigf(B1.y) * c1 + sigf(B1.x) * tanhf(B1.z);
        h1 = sigf(B1.w) * tanhf(c1);
    }

    red[wid][lane] = h0 + h1;
    __syncthreads();
    if (wid == 0) {
        float s = red[0][lane];
        #pragma unroll
        for (int w = 1; w < 8; w++) s += red[w][lane];
        (HOP ? g_final1 : g_final0)[b * 32 + lane] = s;
    }
}

// ---------------- combine: agg matmuls, scores, sigmoid, per-b loss ----------------
__global__ __launch_bounds__(256) void combine_kernel(
        const float* __restrict__ user_table,
        const float* __restrict__ ent_table,
        const float* __restrict__ agg_w,
        const float* __restrict__ agg_b,
        const int* __restrict__ users,
        const int* __restrict__ items,
        const int* __restrict__ ratings,
        float* __restrict__ out, int B) {
    __shared__ float aggT[32 * 32];   // aggT[k*32 + j] = agg_w[j][k]
    __shared__ float aggb_sm[32];
    int tid = threadIdx.x;
    for (int i = tid; i < 32 * 32; i += 256) {
        int k = i >> 5, j = i & 31;
        aggT[i] = agg_w[j * 32 + k];
    }
    if (tid < 32) aggb_sm[tid] = agg_b[tid];
    __syncthreads();

    int wid = tid >> 5, lane = tid & 31;
    int b = blockIdx.x * 8 + wid;
    if (b >= B) return;

    int item = items[b];
    int user = users[b];

    // hop-0 aggregation: emb1 = (ent[item] + final0) @ agg_w^T + agg_b
    float v = ent_table[item * 32 + lane] + g_final0[b * 32 + lane];
    float acc = aggb_sm[lane];
    #pragma unroll
    for (int k = 0; k < 32; k++)
        acc += __shfl_sync(FULL, v, k) * aggT[k * 32 + lane];

    // hop-1 aggregation: emb2 = (emb1 + final1) @ agg_w^T + agg_b
    v = acc + g_final1[b * 32 + lane];
    acc = aggb_sm[lane];
    #pragma unroll
    for (int k = 0; k < 32; k++)
        acc += __shfl_sync(FULL, v, k) * aggT[k * 32 + lane];

    // score = dot(u, emb2)
    float prod = user_table[user * 32 + lane] * acc;
    #pragma unroll
    for (int o = 16; o; o >>= 1) prod += __shfl_xor_sync(FULL, prod, o);

    if (lane == 0) {
        float s = prod;
        out[1 + b]     = 1.0f / (1.0f + __expf(-s));   // sigmoid(score)
        out[1 + B + b] = (float)item;                  // items passthrough
        float r    = (float)ratings[b];
        float ls_p = fminf(s, 0.0f)  - log1pf(__expf(-fabsf(s)));  // log_sigmoid(s)
        float ls_n = fminf(-s, 0.0f) - log1pf(__expf(-fabsf(s)));  // log_sigmoid(-s)
        g_lossbuf[b] = -(r * ls_p + (1.0f - r) * ls_n);
    }
}

// ---------------- loss reduction ----------------
__global__ void loss_kernel(float* __restrict__ out, int B) {
    __shared__ float sm[1024];
    int tid = threadIdx.x;
    float s = 0.f;
    for (int i = tid; i < B; i += 1024) s += g_lossbuf[i];
    sm[tid] = s;
    __syncthreads();
    for (int o = 512; o; o >>= 1) {
        if (tid < o) sm[tid] += sm[tid + o];
        __syncthreads();
    }
    if (tid == 0) out[0] = sm[0] / (float)B;
}

// ---------------- launch ----------------
extern "C" void kernel_launch(void* const* d_in, const int* in_sizes, int n_in,
                              void* d_out, int out_size) {
    const float* user_table = (const float*)d_in[0];
    const float* ent_table  = (const float*)d_in[1];
    const float* rel_table  = (const float*)d_in[2];
    const float* w_ih0      = (const float*)d_in[3];
    const float* w_hh0      = (const float*)d_in[4];
    const float* b_ih0      = (const float*)d_in[5];
    const float* b_hh0      = (const float*)d_in[6];
    const float* w_ih1      = (const float*)d_in[7];
    const float* w_hh1      = (const float*)d_in[8];
    const float* b_ih1      = (const float*)d_in[9];
    const float* b_hh1      = (const float*)d_in[10];
    const float* agg_w      = (const float*)d_in[11];
    const float* agg_b      = (const float*)d_in[12];
    const int*   users      = (const int*)d_in[13];
    const int*   items      = (const int*)d_in[14];
    const int*   ratings    = (const int*)d_in[15];
    const int*   lp0        = (const int*)d_in[16];
    const int*   lp1        = (const int*)d_in[17];
    float*       out        = (float*)d_out;

    int B = in_sizes[13];

    precompute_tables_kernel<<<4, 1024>>>(rel_table, ent_table, w_ih0, w_ih1);
    precompute_u_kernel<<<(B + 7) / 8, 256>>>(user_table, w_ih0, w_ih1, users, B);
    hop_kernel<2, 3, 0><<<B, 256>>>(w_hh0, b_ih0, b_hh0, items, lp0);
    hop_kernel<3, 5, 1><<<B, 256>>>(w_hh1, b_ih1, b_hh1, items, lp1);
    combine_kernel<<<(B + 7) / 8, 256>>>(user_table, ent_table, agg_w, agg_b,
                                         users, items, ratings, out, B);
    loss_kernel<<<1, 1024>>>(out, B);
}

// round 2
// speedup vs baseline: 2.7460x; 2.7460x over previous
#include <cuda_runtime.h>
#include <math.h>

#define FULL 0xffffffffu
typedef unsigned long long u64;

static constexpr int P    = 16;
static constexpr int MAXB = 16384;
static constexpr int NP   = 4;     // paths per warp

// ---------------- scratch (__device__ globals; no allocations) ----------------
__device__ float4 g_Utab0[MAXB * 32];
__device__ float4 g_Utab1[MAXB * 32];
__device__ float4 g_Rtab0[32 * 32];
__device__ float4 g_Etab0[32 * 32];
__device__ float4 g_Rtab1[32 * 32];
__device__ float4 g_Etab1[32 * 32];
__device__ float  g_part0[MAXB * 4 * 32];   // per-(b, warp-task) partial sums of h
__device__ float  g_part1[MAXB * 4 * 32];
__device__ float  g_lossbuf[MAXB];

__device__ __forceinline__ float sigf(float x)  { return __fdividef(1.0f, 1.0f + __expf(-x)); }
__device__ __forceinline__ float htanh(float x) { float e = __expf(-2.0f * x); return __fdividef(1.0f - e, 1.0f + e); }

__device__ __forceinline__ u64 ffma2(u64 a, u64 b, u64 c) {
    u64 d; asm("fma.rn.f32x2 %0,%1,%2,%3;" : "=l"(d) : "l"(a), "l"(b), "l"(c)); return d;
}
__device__ __forceinline__ u64 fadd2(u64 a, u64 b) {
    u64 d; asm("add.rn.f32x2 %0,%1,%2;" : "=l"(d) : "l"(a), "l"(b)); return d;
}
__device__ __forceinline__ u64 pack2(float x) {
    u64 d; asm("mov.b64 %0,{%1,%1};" : "=l"(d) : "f"(x)); return d;
}
__device__ __forceinline__ u64 pack2f(float x, float y) {
    u64 d; asm("mov.b64 %0,{%1,%2};" : "=l"(d) : "f"(x), "f"(y)); return d;
}
__device__ __forceinline__ float2 unpack2(u64 a) {
    float2 f; asm("mov.b64 {%0,%1},%2;" : "=f"(f.x), "=f"(f.y) : "l"(a)); return f;
}

// ---------------- precompute E/R contribution tables (tiny) ----------------
// blockIdx.x: 0 -> Rtab0, 1 -> Etab0, 2 -> Rtab1, 3 -> Etab1
__global__ void precompute_tables_kernel(const float* __restrict__ rel_table,
                                         const float* __restrict__ ent_table,
                                         const float* __restrict__ wih0,
                                         const float* __restrict__ wih1) {
    int tid   = threadIdx.x;          // 1024
    int which = blockIdx.x;
    int r     = tid >> 5;
    int lane  = tid & 31;
    const float* w   = (which < 2) ? wih0 : wih1;
    const float* src = (which & 1) ? ent_table : rel_table;
    int colofs       = (which & 1) ? 32 : 0;

    float4 acc = make_float4(0.f, 0.f, 0.f, 0.f);
    #pragma unroll
    for (int k = 0; k < 32; k++) {
        float x = src[r * 32 + k];
        acc.x += x * w[(0 * 32 + lane) * 64 + colofs + k];
        acc.y += x * w[(1 * 32 + lane) * 64 + colofs + k];
        acc.z += x * w[(2 * 32 + lane) * 64 + colofs + k];
        acc.w += x * w[(3 * 32 + lane) * 64 + colofs + k];
    }
    float4* dst = (which == 0) ? g_Rtab0 : (which == 1) ? g_Etab0
                : (which == 2) ? g_Rtab1 : g_Etab1;
    dst[tid] = acc;
}

// ---------------- precompute per-b user contribution (both hops) ----------------
__global__ __launch_bounds__(256) void precompute_u_kernel(
        const float* __restrict__ user_table,
        const float* __restrict__ wih0,
        const float* __restrict__ wih1,
        const int* __restrict__ users, int B) {
    __shared__ float4 w0[32 * 32];
    __shared__ float4 w1[32 * 32];
    int tid = threadIdx.x;
    for (int i = tid; i < 32 * 32; i += 256) {
        int k = i >> 5, l = i & 31;
        w0[i] = make_float4(wih0[l * 64 + k], wih0[(l + 32) * 64 + k],
                            wih0[(l + 64) * 64 + k], wih0[(l + 96) * 64 + k]);
        w1[i] = make_float4(wih1[l * 64 + k], wih1[(l + 32) * 64 + k],
                            wih1[(l + 64) * 64 + k], wih1[(l + 96) * 64 + k]);
    }
    __syncthreads();

    int wid = tid >> 5, lane = tid & 31;
    int b = blockIdx.x * 8 + wid;
    if (b >= B) return;
    float u = user_table[users[b] * 32 + lane];
    float4 a0 = make_float4(0.f, 0.f, 0.f, 0.f);
    float4 a1 = make_float4(0.f, 0.f, 0.f, 0.f);
    #pragma unroll
    for (int k = 0; k < 32; k++) {
        float uk = __shfl_sync(FULL, u, k);
        float4 q0 = w0[k * 32 + lane];
        float4 q1 = w1[k * 32 + lane];
        a0.x += uk * q0.x; a0.y += uk * q0.y; a0.z += uk * q0.z; a0.w += uk * q0.w;
        a1.x += uk * q1.x; a1.y += uk * q1.y; a1.z += uk * q1.z; a1.w += uk * q1.w;
    }
    g_Utab0[b * 32 + lane] = a0;
    g_Utab1[b * 32 + lane] = a1;
}

// ---------------- main hop kernel ----------------
// Task = (b, quad of 4 paths). lane = hidden dim. Grid-stride over tasks.
template <int NSTEP, int STRIDE, int HOP>
__global__ __launch_bounds__(256, 2) void hop_kernel(
        const float* __restrict__ whh,
        const float* __restrict__ b_ih,
        const float* __restrict__ b_hh,
        const int* __restrict__ items,
        const int* __restrict__ lp, int B) {
    __shared__ ulonglong2 whh_sm[32 * 32];   // [k][lane] -> 4 gate weights as 2×f32x2
    __shared__ float4 h_sm4[8][NP][8];       // per-warp h broadcast buffers

    int tid = threadIdx.x, wid = tid >> 5, lane = tid & 31;
    for (int i = tid; i < 32 * 32; i += 256) {
        int k = i >> 5, l = i & 31;
        float4 w4 = make_float4(whh[l * 32 + k], whh[(l + 32) * 32 + k],
                                whh[(l + 64) * 32 + k], whh[(l + 96) * 32 + k]);
        whh_sm[i] = *reinterpret_cast<ulonglong2*>(&w4);
    }
    __syncthreads();

    const ulonglong2* Utab = reinterpret_cast<const ulonglong2*>(HOP ? g_Utab1 : g_Utab0);
    const ulonglong2* Rtab = reinterpret_cast<const ulonglong2*>(HOP ? g_Rtab1 : g_Rtab0);
    const ulonglong2* Etab = reinterpret_cast<const ulonglong2*>(HOP ? g_Etab1 : g_Etab0);
    float* gpart = HOP ? g_part1 : g_part0;

    u64 bias_lo = pack2f(b_ih[lane]      + b_hh[lane],      b_ih[32 + lane] + b_hh[32 + lane]);
    u64 bias_hi = pack2f(b_ih[64 + lane] + b_hh[64 + lane], b_ih[96 + lane] + b_hh[96 + lane]);

    int gw = blockIdx.x * 8 + wid;
    int TW = gridDim.x * 8;
    int ntask = B * 4;

    for (int task = gw; task < ntask; task += TW) {
        int b = task >> 2, pp = task & 3;
        int item = __ldg(&items[b]);
        const int* lpb = lp + (size_t)item * (P * STRIDE) + (size_t)pp * (NP * STRIDE);

        int idx[NP][STRIDE];
        #pragma unroll
        for (int p = 0; p < NP; p++)
            #pragma unroll
            for (int j = 0; j < STRIDE; j++)
                idx[p][j] = __ldg(&lpb[p * STRIDE + j]);

        ulonglong2 Ub = Utab[b * 32 + lane];
        u64 base_lo = fadd2(bias_lo, Ub.x);
        u64 base_hi = fadd2(bias_hi, Ub.y);

        // ---- step 0: gates = bias + U[b] + E[seed]; h = c = 0 before ----
        float c[NP], h[NP];
        #pragma unroll
        for (int p = 0; p < NP; p++) {
            ulonglong2 E = Etab[idx[p][0] * 32 + lane];
            float2 glo = unpack2(fadd2(base_lo, E.x));   // (i, f)
            float2 ghi = unpack2(fadd2(base_hi, E.y));   // (g, o)
            c[p] = sigf(glo.x) * htanh(ghi.x);
            h[p] = sigf(ghi.y) * htanh(c[p]);
        }

        // ---- steps 1..NSTEP-1: gates = bias + R[rel] + E[tail] + h @ W_hh^T ----
        #pragma unroll
        for (int s = 1; s < NSTEP; s++) {
            __syncwarp();
            #pragma unroll
            for (int p = 0; p < NP; p++)
                reinterpret_cast<float*>(&h_sm4[wid][p][0])[lane] = h[p];
            __syncwarp();

            u64 Blo[NP], Bhi[NP];
            #pragma unroll
            for (int p = 0; p < NP; p++) {
                ulonglong2 R = Rtab[idx[p][2 * s - 1] * 32 + lane];
                ulonglong2 T = Etab[idx[p][2 * s]     * 32 + lane];
                Blo[p] = fadd2(fadd2(bias_lo, R.x), T.x);
                Bhi[p] = fadd2(fadd2(bias_hi, R.y), T.y);
            }
            #pragma unroll
            for (int j = 0; j < 8; j++) {
                float4 h4[NP];
                #pragma unroll
                for (int p = 0; p < NP; p++) h4[p] = h_sm4[wid][p][j];   // broadcast LDS.128
                #pragma unroll
                for (int kk = 0; kk < 4; kk++) {
                    ulonglong2 w2 = whh_sm[(j * 4 + kk) * 32 + lane];
                    #pragma unroll
                    for (int p = 0; p < NP; p++) {
                        float hk = (kk == 0) ? h4[p].x : (kk == 1) ? h4[p].y
                                 : (kk == 2) ? h4[p].z : h4[p].w;
                        u64 hp = pack2(hk);
                        Blo[p] = ffma2(hp, w2.x, Blo[p]);
                        Bhi[p] = ffma2(hp, w2.y, Bhi[p]);
                    }
                }
            }
            #pragma unroll
            for (int p = 0; p < NP; p++) {
                float2 glo = unpack2(Blo[p]);   // (i, f)
                float2 ghi = unpack2(Bhi[p]);   // (g, o)
                c[p] = sigf(glo.y) * c[p] + sigf(glo.x) * htanh(ghi.x);
                h[p] = sigf(ghi.y) * htanh(c[p]);
            }
        }

        gpart[task * 32 + lane] = h[0] + h[1] + h[2] + h[3];
    }
}

// ---------------- combine: agg matmuls, scores, sigmoid, per-b loss ----------------
__global__ __launch_bounds__(256) void combine_kernel(
        const float* __restrict__ user_table,
        const float* __restrict__ ent_table,
        const float* __restrict__ agg_w,
        const float* __restrict__ agg_b,
        const int* __restrict__ users,
        const int* __restrict__ items,
        const int* __restrict__ ratings,
        float* __restrict__ out, int B) {
    __shared__ float aggT[32 * 32];   // aggT[k*32 + j] = agg_w[j][k]
    __shared__ float aggb_sm[32];
    int tid = threadIdx.x;
    for (int i = tid; i < 32 * 32; i += 256) {
        int k = i >> 5, j = i & 31;
        aggT[i] = agg_w[j * 32 + k];
    }
    if (tid < 32) aggb_sm[tid] = agg_b[tid];
    __syncthreads();

    int wid = tid >> 5, lane = tid & 31;
    int b = blockIdx.x * 8 + wid;
    if (b >= B) return;

    int item = items[b];
    int user = users[b];

    float f0 = 0.f, f1 = 0.f;
    #pragma unroll
    for (int j = 0; j < 4; j++) {
        f0 += g_part0[(b * 4 + j) * 32 + lane];
        f1 += g_part1[(b * 4 + j) * 32 + lane];
    }

    // hop-0 aggregation: emb1 = (ent[item] + final0) @ agg_w^T + agg_b
    float v = ent_table[item * 32 + lane] + f0;
    float acc = aggb_sm[lane];
    #pragma unroll
    for (int k = 0; k < 32; k++)
        acc += __shfl_sync(FULL, v, k) * aggT[k * 32 + lane];

    // hop-1 aggregation
    v = acc + f1;
    acc = aggb_sm[lane];
    #pragma unroll
    for (int k = 0; k < 32; k++)
        acc += __shfl_sync(FULL, v, k) * aggT[k * 32 + lane];

    // score = dot(u, emb2)
    float prod = user_table[user * 32 + lane] * acc;
    #pragma unroll
    for (int o = 16; o; o >>= 1) prod += __shfl_xor_sync(FULL, prod, o);

    if (lane == 0) {
        float s = prod;
        out[1 + b]     = 1.0f / (1.0f + __expf(-s));
        out[1 + B + b] = (float)item;
        float r    = (float)ratings[b];
        float ls_p = fminf(s, 0.0f)  - log1pf(__expf(-fabsf(s)));
        float ls_n = fminf(-s, 0.0f) - log1pf(__expf(-fabsf(s)));
        g_lossbuf[b] = -(r * ls_p + (1.0f - r) * ls_n);
    }
}

// ---------------- loss reduction ----------------
__global__ void loss_kernel(float* __restrict__ out, int B) {
    __shared__ float sm[1024];
    int tid = threadIdx.x;
    float s = 0.f;
    for (int i = tid; i < B; i += 1024) s += g_lossbuf[i];
    sm[tid] = s;
    __syncthreads();
    for (int o = 512; o; o >>= 1) {
        if (tid < o) sm[tid] += sm[tid + o];
        __syncthreads();
    }
    if (tid == 0) out[0] = sm[0] / (float)B;
}

// ---------------- launch ----------------
extern "C" void kernel_launch(void* const* d_in, const int* in_sizes, int n_in,
                              void* d_out, int out_size) {
    const float* user_table = (const float*)d_in[0];
    const float* ent_table  = (const float*)d_in[1];
    const float* rel_table  = (const float*)d_in[2];
    const float* w_ih0      = (const float*)d_in[3];
    const float* w_hh0      = (const float*)d_in[4];
    const float* b_ih0      = (const float*)d_in[5];
    const float* b_hh0      = (const float*)d_in[6];
    const float* w_ih1      = (const float*)d_in[7];
    const float* w_hh1      = (const float*)d_in[8];
    const float* b_ih1      = (const float*)d_in[9];
    const float* b_hh1      = (const float*)d_in[10];
    const float* agg_w      = (const float*)d_in[11];
    const float* agg_b      = (const float*)d_in[12];
    const int*   users      = (const int*)d_in[13];
    const int*   items      = (const int*)d_in[14];
    const int*   ratings    = (const int*)d_in[15];
    const int*   lp0        = (const int*)d_in[16];
    const int*   lp1        = (const int*)d_in[17];
    float*       out        = (float*)d_out;

    int B = in_sizes[13];

    precompute_tables_kernel<<<4, 1024>>>(rel_table, ent_table, w_ih0, w_ih1);
    precompute_u_kernel<<<(B + 7) / 8, 256>>>(user_table, w_ih0, w_ih1, users, B);
    hop_kernel<2, 3, 0><<<296, 256>>>(w_hh0, b_ih0, b_hh0, items, lp0, B);
    hop_kernel<3, 5, 1><<<296, 256>>>(w_hh1, b_ih1, b_hh1, items, lp1, B);
    combine_kernel<<<(B + 7) / 8, 256>>>(user_table, ent_table, agg_w, agg_b,
                                         users, items, ratings, out, B);
    loss_kernel<<<1, 1024>>>(out, B);
}

// round 3
// speedup vs baseline: 3.0686x; 1.1175x over previous
#include <cuda_runtime.h>
#include <math.h>

#define FULL 0xffffffffu
typedef unsigned long long u64;
typedef unsigned int u32;

static constexpr int P    = 16;
static constexpr int MAXB = 16384;
static constexpr int NP   = 8;       // paths per warp
static constexpr int NBLK = 296;     // persistent grid (148 SMs x 2 CTA)
static constexpr int NBLK0 = 99;     // fused-hop blocks for hop0 (1:2 work split)

// ---------------- scratch (__device__ globals; no allocations) ----------------
__device__ float4 g_Utab0[MAXB * 32];
__device__ float4 g_Utab1[MAXB * 32];
__device__ float4 g_Rtab0[32 * 32];
__device__ float4 g_Etab0[32 * 32];
__device__ float4 g_Rtab1[32 * 32];
__device__ float4 g_Etab1[32 * 32];
__device__ float  g_part0[MAXB * 2 * 32];   // per-(b, task-half) partial sums of h
__device__ float  g_part1[MAXB * 2 * 32];
__device__ float  g_lossblk[NBLK];

__device__ __forceinline__ float sigf(float x)  { return __fdividef(1.0f, 1.0f + __expf(-x)); }
__device__ __forceinline__ float htanh(float x) { float e = __expf(-2.0f * x); return __fdividef(1.0f - e, 1.0f + e); }

__device__ __forceinline__ u64 ffma2(u64 a, u64 b, u64 c) {
    u64 d; asm("fma.rn.f32x2 %0,%1,%2,%3;" : "=l"(d) : "l"(a), "l"(b), "l"(c)); return d;
}
__device__ __forceinline__ u64 fadd2(u64 a, u64 b) {
    u64 d; asm("add.rn.f32x2 %0,%1,%2;" : "=l"(d) : "l"(a), "l"(b)); return d;
}
__device__ __forceinline__ u64 pack2(float x) {
    u64 d; asm("mov.b64 %0,{%1,%1};" : "=l"(d) : "f"(x)); return d;
}
__device__ __forceinline__ u64 pack2f(float x, float y) {
    u64 d; asm("mov.b64 %0,{%1,%2};" : "=l"(d) : "f"(x), "f"(y)); return d;
}
__device__ __forceinline__ float2 unpack2(u64 a) {
    float2 f; asm("mov.b64 {%0,%1},%2;" : "=f"(f.x), "=f"(f.y) : "l"(a)); return f;
}

// ---------------- precompute E/R contribution tables (tiny) ----------------
__global__ void precompute_tables_kernel(const float* __restrict__ rel_table,
                                         const float* __restrict__ ent_table,
                                         const float* __restrict__ wih0,
                                         const float* __restrict__ wih1) {
    int tid   = threadIdx.x;          // 1024
    int which = blockIdx.x;           // 0:Rtab0 1:Etab0 2:Rtab1 3:Etab1
    int r     = tid >> 5;
    int lane  = tid & 31;
    const float* w   = (which < 2) ? wih0 : wih1;
    const float* src = (which & 1) ? ent_table : rel_table;
    int colofs       = (which & 1) ? 32 : 0;

    float4 acc = make_float4(0.f, 0.f, 0.f, 0.f);
    #pragma unroll
    for (int k = 0; k < 32; k++) {
        float x = src[r * 32 + k];
        acc.x += x * w[(0 * 32 + lane) * 64 + colofs + k];
        acc.y += x * w[(1 * 32 + lane) * 64 + colofs + k];
        acc.z += x * w[(2 * 32 + lane) * 64 + colofs + k];
        acc.w += x * w[(3 * 32 + lane) * 64 + colofs + k];
    }
    float4* dst = (which == 0) ? g_Rtab0 : (which == 1) ? g_Etab0
                : (which == 2) ? g_Rtab1 : g_Etab1;
    dst[tid] = acc;
}

// ---------------- precompute per-b user contribution (persistent grid) ----------------
__global__ __launch_bounds__(256) void precompute_u_kernel(
        const float* __restrict__ user_table,
        const float* __restrict__ wih0,
        const float* __restrict__ wih1,
        const int* __restrict__ users, int B) {
    __shared__ float4 w0[32 * 32];
    __shared__ float4 w1[32 * 32];
    int tid = threadIdx.x;
    for (int i = tid; i < 32 * 32; i += 256) {
        int k = i >> 5, l = i & 31;
        w0[i] = make_float4(wih0[l * 64 + k], wih0[(l + 32) * 64 + k],
                            wih0[(l + 64) * 64 + k], wih0[(l + 96) * 64 + k]);
        w1[i] = make_float4(wih1[l * 64 + k], wih1[(l + 32) * 64 + k],
                            wih1[(l + 64) * 64 + k], wih1[(l + 96) * 64 + k]);
    }
    __syncthreads();

    int wid = tid >> 5, lane = tid & 31;
    int gw = blockIdx.x * 8 + wid, TW = gridDim.x * 8;
    for (int b = gw; b < B; b += TW) {
        float u = user_table[users[b] * 32 + lane];
        float4 a0 = make_float4(0.f, 0.f, 0.f, 0.f);
        float4 a1 = make_float4(0.f, 0.f, 0.f, 0.f);
        #pragma unroll
        for (int k = 0; k < 32; k++) {
            float uk = __shfl_sync(FULL, u, k);
            float4 q0 = w0[k * 32 + lane];
            float4 q1 = w1[k * 32 + lane];
            a0.x += uk * q0.x; a0.y += uk * q0.y; a0.z += uk * q0.z; a0.w += uk * q0.w;
            a1.x += uk * q1.x; a1.y += uk * q1.y; a1.z += uk * q1.z; a1.w += uk * q1.w;
        }
        g_Utab0[b * 32 + lane] = a0;
        g_Utab1[b * 32 + lane] = a1;
    }
}

// ---------------- hop body: 8 paths/warp, pre-packed h, f32x2 FFMAs ----------------
template <int NSTEP, int STRIDE, int HOP>
__device__ __forceinline__ void hop_body(
        ulonglong2* whh_sm, u64* hp_sm,
        const float* __restrict__ whh,
        const float* __restrict__ b_ih,
        const float* __restrict__ b_hh,
        const int* __restrict__ items,
        const int* __restrict__ lp,
        int B, int blk, int nblk) {
    int tid = threadIdx.x, wid = tid >> 5, lane = tid & 31;

    for (int i = tid; i < 32 * 32; i += 256) {
        int k = i >> 5, l = i & 31;
        float4 w4 = make_float4(whh[l * 32 + k], whh[(l + 32) * 32 + k],
                                whh[(l + 64) * 32 + k], whh[(l + 96) * 32 + k]);
        whh_sm[i] = *reinterpret_cast<ulonglong2*>(&w4);
    }
    __syncthreads();

    const ulonglong2* Utab = reinterpret_cast<const ulonglong2*>(HOP ? g_Utab1 : g_Utab0);
    const ulonglong2* Rtab = reinterpret_cast<const ulonglong2*>(HOP ? g_Rtab1 : g_Rtab0);
    const ulonglong2* Etab = reinterpret_cast<const ulonglong2*>(HOP ? g_Etab1 : g_Etab0);
    float* gpart = HOP ? g_part1 : g_part0;

    u64 bias_lo = pack2f(b_ih[lane]      + b_hh[lane],      b_ih[32 + lane] + b_hh[32 + lane]);
    u64 bias_hi = pack2f(b_ih[64 + lane] + b_hh[64 + lane], b_ih[96 + lane] + b_hh[96 + lane]);

    u64* hpw = hp_sm + wid * (NP * 32);     // this warp's packed-h region

    int gw = blk * 8 + wid;
    int TW = nblk * 8;
    int ntask = B * 2;                       // task = (b, half of 8 paths)

    for (int task = gw; task < ntask; task += TW) {
        int b = task >> 1, half = task & 1;
        int item = __ldg(&items[b]);
        const int* lpb = lp + (size_t)item * (P * STRIDE) + (size_t)half * (NP * STRIDE);

        // pack indices: 5 bits each (values are in [0,32))
        u32 ipack[NP];
        #pragma unroll
        for (int p = 0; p < NP; p++) {
            u32 v = 0;
            #pragma unroll
            for (int j = 0; j < STRIDE; j++)
                v |= ((u32)__ldg(&lpb[p * STRIDE + j])) << (5 * j);
            ipack[p] = v;
        }

        ulonglong2 Ub = Utab[b * 32 + lane];
        u64 base_lo = fadd2(bias_lo, Ub.x);
        u64 base_hi = fadd2(bias_hi, Ub.y);

        // ---- step 0: gates = bias + U[b] + E[seed]; (h,c)=0 before ----
        float c[NP], h[NP];
        #pragma unroll
        for (int p = 0; p < NP; p++) {
            ulonglong2 E = Etab[(ipack[p] & 31) * 32 + lane];
            float2 glo = unpack2(fadd2(base_lo, E.x));   // (i, f)
            float2 ghi = unpack2(fadd2(base_hi, E.y));   // (g, o)
            c[p] = sigf(glo.x) * htanh(ghi.x);
            h[p] = sigf(ghi.y) * htanh(c[p]);
        }

        // ---- steps 1..NSTEP-1 ----
        #pragma unroll
        for (int s = 1; s < NSTEP; s++) {
            __syncwarp();
            #pragma unroll
            for (int p = 0; p < NP; p++)
                hpw[p * 32 + lane] = pack2(h[p]);        // STS.64 {h,h}
            __syncwarp();

            u64 Blo[NP], Bhi[NP];
            #pragma unroll
            for (int p = 0; p < NP; p++) {
                int ri = (ipack[p] >> (5 * (2 * s - 1))) & 31;
                int ti = (ipack[p] >> (5 * (2 * s)))     & 31;
                ulonglong2 R = Rtab[ri * 32 + lane];
                ulonglong2 T = Etab[ti * 32 + lane];
                Blo[p] = fadd2(fadd2(bias_lo, R.x), T.x);
                Bhi[p] = fadd2(fadd2(bias_hi, R.y), T.y);
            }
            #pragma unroll
            for (int j = 0; j < 8; j++) {
                ulonglong2 w0 = whh_sm[(4 * j + 0) * 32 + lane];
                ulonglong2 w1 = whh_sm[(4 * j + 1) * 32 + lane];
                ulonglong2 w2 = whh_sm[(4 * j + 2) * 32 + lane];
                ulonglong2 w3 = whh_sm[(4 * j + 3) * 32 + lane];
                #pragma unroll
                for (int p = 0; p < NP; p++) {
                    ulonglong2 ha = *reinterpret_cast<ulonglong2*>(&hpw[p * 32 + 4 * j]);
                    ulonglong2 hb = *reinterpret_cast<ulonglong2*>(&hpw[p * 32 + 4 * j + 2]);
                    Blo[p] = ffma2(ha.x, w0.x, Blo[p]); Bhi[p] = ffma2(ha.x, w0.y, Bhi[p]);
                    Blo[p] = ffma2(ha.y, w1.x, Blo[p]); Bhi[p] = ffma2(ha.y, w1.y, Bhi[p]);
                    Blo[p] = ffma2(hb.x, w2.x, Blo[p]); Bhi[p] = ffma2(hb.x, w2.y, Bhi[p]);
                    Blo[p] = ffma2(hb.y, w3.x, Blo[p]); Bhi[p] = ffma2(hb.y, w3.y, Bhi[p]);
                }
            }
            #pragma unroll
            for (int p = 0; p < NP; p++) {
                float2 glo = unpack2(Blo[p]);   // (i, f)
                float2 ghi = unpack2(Bhi[p]);   // (g, o)
                c[p] = sigf(glo.y) * c[p] + sigf(glo.x) * htanh(ghi.x);
                h[p] = sigf(ghi.y) * htanh(c[p]);
            }
        }

        float hs = 0.f;
        #pragma unroll
        for (int p = 0; p < NP; p++) hs += h[p];
        gpart[task * 32 + lane] = hs;
    }
}

// ---------------- fused hop kernel: both hops run concurrently ----------------
__global__ __launch_bounds__(256, 2) void fused_hop_kernel(
        const float* __restrict__ whh0, const float* __restrict__ bih0, const float* __restrict__ bhh0,
        const float* __restrict__ whh1, const float* __restrict__ bih1, const float* __restrict__ bhh1,
        const int* __restrict__ items,
        const int* __restrict__ lp0, const int* __restrict__ lp1, int B) {
    __shared__ ulonglong2 whh_sm[32 * 32];   // 16 KB
    __shared__ u64 hp_sm[8 * NP * 32];       // 16 KB packed {h,h}

    if (blockIdx.x < NBLK0)
        hop_body<2, 3, 0>(whh_sm, hp_sm, whh0, bih0, bhh0, items, lp0, B, blockIdx.x, NBLK0);
    else
        hop_body<3, 5, 1>(whh_sm, hp_sm, whh1, bih1, bhh1, items, lp1, B, blockIdx.x - NBLK0, NBLK - NBLK0);
}

// ---------------- combine: agg matmuls, scores, sigmoid, block loss partials ----------------
__global__ __launch_bounds__(256) void combine_kernel(
        const float* __restrict__ user_table,
        const float* __restrict__ ent_table,
        const float* __restrict__ agg_w,
        const float* __restrict__ agg_b,
        const int* __restrict__ users,
        const int* __restrict__ items,
        const int* __restrict__ ratings,
        float* __restrict__ out, int B) {
    __shared__ float aggT[32 * 32];
    __shared__ float aggb_sm[32];
    __shared__ float lred[8];
    int tid = threadIdx.x;
    for (int i = tid; i < 32 * 32; i += 256) {
        int k = i >> 5, j = i & 31;
        aggT[i] = agg_w[j * 32 + k];
    }
    if (tid < 32) aggb_sm[tid] = agg_b[tid];
    __syncthreads();

    int wid = tid >> 5, lane = tid & 31;
    int gw = blockIdx.x * 8 + wid, TW = gridDim.x * 8;
    float loss_acc = 0.f;

    for (int b = gw; b < B; b += TW) {
        int item = items[b];
        int user = users[b];

        float f0 = g_part0[(b * 2 + 0) * 32 + lane] + g_part0[(b * 2 + 1) * 32 + lane];
        float f1 = g_part1[(b * 2 + 0) * 32 + lane] + g_part1[(b * 2 + 1) * 32 + lane];

        // hop-0 aggregation: emb1 = (ent[item] + final0) @ agg_w^T + agg_b
        float v = ent_table[item * 32 + lane] + f0;
        float acc = aggb_sm[lane];
        #pragma unroll
        for (int k = 0; k < 32; k++)
            acc += __shfl_sync(FULL, v, k) * aggT[k * 32 + lane];

        // hop-1 aggregation
        v = acc + f1;
        acc = aggb_sm[lane];
        #pragma unroll
        for (int k = 0; k < 32; k++)
            acc += __shfl_sync(FULL, v, k) * aggT[k * 32 + lane];

        // score = dot(u, emb2)
        float prod = user_table[user * 32 + lane] * acc;
        #pragma unroll
        for (int o = 16; o; o >>= 1) prod += __shfl_xor_sync(FULL, prod, o);

        if (lane == 0) {
            float s = prod;
            out[1 + b]     = 1.0f / (1.0f + __expf(-s));
            out[1 + B + b] = (float)item;
            float r    = (float)ratings[b];
            float ls_p = fminf(s, 0.0f)  - log1pf(__expf(-fabsf(s)));
            float ls_n = fminf(-s, 0.0f) - log1pf(__expf(-fabsf(s)));
            loss_acc += -(r * ls_p + (1.0f - r) * ls_n);
        }
    }

    if (lane == 0) lred[wid] = loss_acc;
    __syncthreads();
    if (tid == 0) {
        float s = 0.f;
        #pragma unroll
        for (int w = 0; w < 8; w++) s += lred[w];
        g_lossblk[blockIdx.x] = s;
    }
}

// ---------------- final loss reduction ----------------
__global__ void loss_kernel(float* __restrict__ out, int B, int nblk) {
    __shared__ float sm[512];
    int tid = threadIdx.x;
    float s = 0.f;
    for (int i = tid; i < nblk; i += 512) s += g_lossblk[i];
    sm[tid] = s;
    __syncthreads();
    for (int o = 256; o; o >>= 1) {
        if (tid < o) sm[tid] += sm[tid + o];
        __syncthreads();
    }
    if (tid == 0) out[0] = sm[0] / (float)B;
}

// ---------------- launch ----------------
extern "C" void kernel_launch(void* const* d_in, const int* in_sizes, int n_in,
                              void* d_out, int out_size) {
    const float* user_table = (const float*)d_in[0];
    const float* ent_table  = (const float*)d_in[1];
    const float* rel_table  = (const float*)d_in[2];
    const float* w_ih0      = (const float*)d_in[3];
    const float* w_hh0      = (const float*)d_in[4];
    const float* b_ih0      = (const float*)d_in[5];
    const float* b_hh0      = (const float*)d_in[6];
    const float* w_ih1      = (const float*)d_in[7];
    const float* w_hh1      = (const float*)d_in[8];
    const float* b_ih1      = (const float*)d_in[9];
    const float* b_hh1      = (const float*)d_in[10];
    const float* agg_w      = (const float*)d_in[11];
    const float* agg_b      = (const float*)d_in[12];
    const int*   users      = (const int*)d_in[13];
    const int*   items      = (const int*)d_in[14];
    const int*   ratings    = (const int*)d_in[15];
    const int*   lp0        = (const int*)d_in[16];
    const int*   lp1        = (const int*)d_in[17];
    float*       out        = (float*)d_out;

    int B = in_sizes[13];

    precompute_tables_kernel<<<4, 1024>>>(rel_table, ent_table, w_ih0, w_ih1);
    precompute_u_kernel<<<NBLK, 256>>>(user_table, w_ih0, w_ih1, users, B);
    fused_hop_kernel<<<NBLK, 256>>>(w_hh0, b_ih0, b_hh0, w_hh1, b_ih1, b_hh1,
                                    items, lp0, lp1, B);
    combine_kernel<<<NBLK, 256>>>(user_table, ent_table, agg_w, agg_b,
                                  users, items, ratings, out, B);
    loss_kernel<<<1, 512>>>(out, B, NBLK);
}